// round 1
// baseline (speedup 1.0000x reference)
#include <cuda_runtime.h>
#include <math.h>

#define NB   4
#define NS   4224
#define ND   1024
#define NDM  64
#define NDK  128
#define NL   528
#define NSEG 8
#define NM   16
#define EPSV 1e-5f

// ---------------- device scratch (static, allocation-free) ----------------
__device__ float g_Q[NB*NS*NDK];               // dpfp(hs @ W_mq), 8.65 MB
__device__ float g_W[(NSEG+1)*NB*NDK*ND];      // W_mem history, 18.9 MB
__device__ float g_z[(NSEG+1)*NB*NDK];         // z history
__device__ float g_mem[NB*NM*ND];              // mem tokens (assoc + mo)
__device__ float g_xp[NB*4*NM*NDM];            // partial x = mem @ W_mk (4 K-quads)
__device__ float g_k[NB*NM*NDK];               // dpfp(mem @ W_mk)
__device__ float g_kz[NB*NM];                  // k . z
__device__ float g_v[NB*NM*ND];                // mem @ W_mv
__device__ float g_g[NB*NM*ND];                // mem @ W_mb + b_mb (pre-sigmoid)
__device__ float g_p[NB*NM*ND];                // k @ W_mem (prev numerator)

// ---------------- init: zero W_hist[0], z_hist[0] ----------------
__global__ void k_init()
{
    int i = blockIdx.x * blockDim.x + threadIdx.x;
    if (i < NB*NDK*ND) g_W[i] = 0.f;
    if (i < NB*NDK)    g_z[i] = 0.f;
}

// ---------------- K0: Q = dpfp(hs @ W_mq), all tokens in parallel ----------------
// grid 132 blocks x 256 thr; block = 128 rows x 64 cols, K=1024, BK=16
__global__ void k0_projq(const float* __restrict__ hs, const float* __restrict__ Wmq)
{
    __shared__ float As[16*128];   // [k][m]
    __shared__ float Bs[16*64];    // [k][n]
    __shared__ float Xs[128*65];   // x tile for dpfp epilogue (pad 1)
    int tid = threadIdx.x;
    int rowBase = blockIdx.x * 128;
    int tx = tid & 15, ty = tid >> 4;
    float acc[8][4];
    #pragma unroll
    for (int i = 0; i < 8; i++)
        #pragma unroll
        for (int j = 0; j < 4; j++) acc[i][j] = 0.f;

    for (int k0 = 0; k0 < ND; k0 += 16) {
        #pragma unroll
        for (int it = 0; it < 2; it++) {          // A: 128x16 = 512 float4
            int f = it*256 + tid;
            int row = f >> 2; int q = (f & 3) * 4;
            float4 v4 = *reinterpret_cast<const float4*>(
                &hs[(size_t)(rowBase + row)*ND + k0 + q]);
            As[(q+0)*128+row] = v4.x; As[(q+1)*128+row] = v4.y;
            As[(q+2)*128+row] = v4.z; As[(q+3)*128+row] = v4.w;
        }
        {                                          // B: 16x64 = 256 float4
            int f = tid;
            int kr = f >> 4; int c = (f & 15) * 4;
            *reinterpret_cast<float4*>(&Bs[kr*64 + c]) =
                *reinterpret_cast<const float4*>(&Wmq[(size_t)(k0+kr)*NDM + c]);
        }
        __syncthreads();
        #pragma unroll
        for (int k = 0; k < 16; k++) {
            float ra[8], rb[4];
            #pragma unroll
            for (int i = 0; i < 8; i++) ra[i] = As[k*128 + ty*8 + i];
            #pragma unroll
            for (int j = 0; j < 4; j++) rb[j] = Bs[k*64 + tx*4 + j];
            #pragma unroll
            for (int i = 0; i < 8; i++)
                #pragma unroll
                for (int j = 0; j < 4; j++) acc[i][j] += ra[i]*rb[j];
        }
        __syncthreads();
    }
    #pragma unroll
    for (int i = 0; i < 8; i++)
        #pragma unroll
        for (int j = 0; j < 4; j++)
            Xs[(ty*8+i)*65 + tx*4 + j] = acc[i][j];
    __syncthreads();
    // dpfp: x2 = [relu(x), relu(-x)]; out[i] = x2[i]*x2[(i-1) mod 128]
    #pragma unroll
    for (int t = 0; t < 64; t++) {
        int idx = t*256 + tid;
        int row = idx >> 7, i = idx & 127;
        int im1 = (i + 127) & 127;
        float a = (i  < 64) ? fmaxf( Xs[row*65 + i     ], 0.f)
                            : fmaxf(-Xs[row*65 + i - 64], 0.f);
        float b = (im1 < 64) ? fmaxf( Xs[row*65 + im1     ], 0.f)
                             : fmaxf(-Xs[row*65 + im1 - 64], 0.f);
        g_Q[(size_t)(rowBase + row)*NDK + i] = a*b;
    }
}

// ---------------- K1: assoc for 16 mem tokens; mem = assoc + mo ----------------
// grid 64 blocks (b x 16 coltiles of 64) x 256 thr
__global__ void k1_assoc(const float* __restrict__ mo, int seg)
{
    __shared__ float Qs[NM*NDK];
    __shared__ float zs[NDK];
    __shared__ float denp[NM*16];
    __shared__ float den_s[NM];
    int tid = threadIdx.x;
    int b  = blockIdx.x >> 4;
    int cb = (blockIdx.x & 15) * 64;
    const float* Wp = &g_W[((size_t)seg*NB + b)*NDK*ND];
    const float* zp = &g_z[((size_t)seg*NB + b)*NDK];

    for (int f = tid; f < NM*NDK/4; f += 256) {   // 512 float4
        int m = f >> 5; int q = (f & 31) * 4;
        int s = seg*NL + (NL - NM) + m;
        *reinterpret_cast<float4*>(&Qs[m*NDK + q]) =
            *reinterpret_cast<const float4*>(&g_Q[((size_t)b*NS + s)*NDK + q]);
    }
    if (tid < NDK) zs[tid] = zp[tid];
    __syncthreads();
    {
        int m = tid >> 4, part = tid & 15;
        float p = 0.f;
        #pragma unroll
        for (int kk = part*8; kk < part*8 + 8; kk++) p += Qs[m*NDK + kk]*zs[kk];
        denp[m*16 + part] = p;
    }
    __syncthreads();
    if (tid < NM) {
        float s = 0.f;
        #pragma unroll
        for (int j = 0; j < 16; j++) s += denp[tid*16 + j];
        den_s[tid] = s + EPSV;
    }
    __syncthreads();
    int c = tid & 63, rg = tid >> 6;
    float acc[4] = {0.f, 0.f, 0.f, 0.f};
    #pragma unroll 4
    for (int kk = 0; kk < NDK; kk++) {
        float w = Wp[(size_t)kk*ND + cb + c];
        #pragma unroll
        for (int i = 0; i < 4; i++) acc[i] += Qs[(rg*4+i)*NDK + kk]*w;
    }
    #pragma unroll
    for (int i = 0; i < 4; i++) {
        int m = rg*4 + i;
        int s = seg*NL + (NL - NM) + m;
        size_t oo = ((size_t)b*NS + s)*ND + cb + c;
        g_mem[((size_t)b*NM + m)*ND + cb + c] = acc[i]/den_s[m] + mo[oo];
    }
}

// ---------------- K2a: partial x = mem @ W_mk (split over 4 K-quads) ----------------
// grid 16 blocks (b x quad) x 256 thr
__global__ void k2a_x(int seg, const float* __restrict__ Wmk)
{
    __shared__ float As[NM*256];   // mem chunk [m][kk]
    __shared__ float xp[4*NM*64];  // per-part partials
    int tid = threadIdx.x;
    int b = blockIdx.x >> 2, quad = blockIdx.x & 3;
    int kb = quad * 256;
    #pragma unroll
    for (int it = 0; it < 4; it++) {               // 1024 float4
        int f = it*256 + tid;
        int m = f >> 6; int q = (f & 63) * 4;
        *reinterpret_cast<float4*>(&As[m*256 + q]) =
            *reinterpret_cast<const float4*>(&g_mem[((size_t)b*NM + m)*ND + kb + q]);
    }
    __syncthreads();
    int c = tid & 63, part = tid >> 6;
    float acc[NM];
    #pragma unroll
    for (int m = 0; m < NM; m++) acc[m] = 0.f;
    for (int kk = part*64; kk < part*64 + 64; kk++) {
        float w = Wmk[(size_t)(kb + kk)*NDM + c];
        #pragma unroll
        for (int m = 0; m < NM; m++) acc[m] += As[m*256 + kk]*w;
    }
    #pragma unroll
    for (int m = 0; m < NM; m++) xp[part*NM*64 + m*64 + c] = acc[m];
    __syncthreads();
    #pragma unroll
    for (int it = 0; it < 4; it++) {
        int f = it*256 + tid;  // m*64+c
        float s = xp[f] + xp[NM*64 + f] + xp[2*NM*64 + f] + xp[3*NM*64 + f];
        g_xp[((size_t)b*4 + quad)*NM*64 + f] = s;
    }
}

// ---------------- K2b: v, pre-gate, and prev numerator (+ k from x) ----------------
// grid 192: [0,128) = v/g sections (64 rows x 16 cols, K=1024)
//           [128,192) = p per (b, 64-coltile): computes k = dpfp(x) first
__global__ void k2b_vgp(int seg, const float* __restrict__ Wmv,
                        const float* __restrict__ Wmb, const float* __restrict__ bmb)
{
    int tid = threadIdx.x;
    int blk = blockIdx.x;
    if (blk < 128) {
        __shared__ float As[32*64];  // [k][row]
        __shared__ float Bs[32*16];
        int sec = blk >> 6;
        int cb  = (blk & 63) * 16;
        const float* Wm = sec ? Wmb : Wmv;
        int tx = tid & 15, ty = tid >> 4;
        float acc[4] = {0.f, 0.f, 0.f, 0.f};
        for (int k0 = 0; k0 < ND; k0 += 32) {
            #pragma unroll
            for (int it = 0; it < 2; it++) {       // A: 64x32 = 512 float4
                int f = it*256 + tid;
                int r = f >> 3; int q = (f & 7) * 4;
                float4 v4 = *reinterpret_cast<const float4*>(
                    &g_mem[(size_t)r*ND + k0 + q]);
                As[(q+0)*64+r] = v4.x; As[(q+1)*64+r] = v4.y;
                As[(q+2)*64+r] = v4.z; As[(q+3)*64+r] = v4.w;
            }
            #pragma unroll
            for (int it = 0; it < 2; it++) {       // B: 32x16 = 512 floats
                int f = it*256 + tid;
                int kr = f >> 4; int c = f & 15;
                Bs[kr*16 + c] = Wm[(size_t)(k0 + kr)*ND + cb + c];
            }
            __syncthreads();
            #pragma unroll
            for (int k = 0; k < 32; k++) {
                float bv = Bs[k*16 + tx];
                #pragma unroll
                for (int i = 0; i < 4; i++) acc[i] += As[k*64 + ty*4 + i]*bv;
            }
            __syncthreads();
        }
        float badd = sec ? bmb[cb + tx] : 0.f;
        float* dst = sec ? g_g : g_v;
        #pragma unroll
        for (int i = 0; i < 4; i++)
            dst[(size_t)(ty*4 + i)*ND + cb + tx] = acc[i] + badd;
    } else {
        __shared__ float xs[NM*64];
        __shared__ float ksm[NM*NDK];
        __shared__ float zsm[NDK];
        __shared__ float kzp[NM*16];
        int pb = blk - 128;
        int b = pb >> 4, cb = (pb & 15) * 64;
        if (tid < NDK) zsm[tid] = g_z[((size_t)seg*NB + b)*NDK + tid];
        #pragma unroll
        for (int it = 0; it < 4; it++) {           // sum x quads
            int f = it*256 + tid;
            float s = 0.f;
            #pragma unroll
            for (int q = 0; q < 4; q++) s += g_xp[((size_t)b*4 + q)*NM*64 + f];
            xs[f] = s;
        }
        __syncthreads();
        #pragma unroll
        for (int it = 0; it < 8; it++) {           // dpfp -> k  (16x128)
            int f = it*256 + tid;
            int m = f >> 7, i = f & 127;
            int im1 = (i + 127) & 127;
            float a = (i  < 64) ? fmaxf( xs[m*64 + i     ], 0.f)
                                : fmaxf(-xs[m*64 + i - 64], 0.f);
            float b2 = (im1 < 64) ? fmaxf( xs[m*64 + im1     ], 0.f)
                                  : fmaxf(-xs[m*64 + im1 - 64], 0.f);
            float kv = a*b2;
            ksm[m*NDK + i] = kv;
            if ((pb & 15) == 0) g_k[((size_t)b*NM + m)*NDK + i] = kv;
        }
        __syncthreads();
        if ((pb & 15) == 0) {                      // kz (only one block per b)
            int m = tid >> 4, p = tid & 15;
            float s = 0.f;
            #pragma unroll
            for (int i = p*8; i < p*8 + 8; i++) s += ksm[m*NDK + i]*zsm[i];
            kzp[m*16 + p] = s;
        }
        __syncthreads();
        if ((pb & 15) == 0 && tid < NM) {
            float s = 0.f;
            #pragma unroll
            for (int j = 0; j < 16; j++) s += kzp[tid*16 + j];
            g_kz[b*NM + tid] = s;
        }
        // prev numerator: p = k @ W_mem  (16 rows x 64 cols, K=128)
        const float* Wp = &g_W[((size_t)seg*NB + b)*NDK*ND];
        int c = tid & 63, rg = tid >> 6;
        float acc[4] = {0.f, 0.f, 0.f, 0.f};
        #pragma unroll 4
        for (int kk = 0; kk < NDK; kk++) {
            float w = Wp[(size_t)kk*ND + cb + c];
            #pragma unroll
            for (int i = 0; i < 4; i++) acc[i] += ksm[(rg*4 + i)*NDK + kk]*w;
        }
        #pragma unroll
        for (int i = 0; i < 4; i++)
            g_p[((size_t)b*NM + rg*4 + i)*ND + cb + c] = acc[i];
    }
}

// ---------------- K3: new_info, W_hist[seg+1] = W_hist[seg] + k^T @ ni, z update ----------------
// grid 64 blocks (b x 16 coltiles of 64) x 256 thr
__global__ void k3_update(int seg)
{
    __shared__ float ks[NM*NDK];
    __shared__ float nis[NM*64];
    int tid = threadIdx.x;
    int b  = blockIdx.x >> 4;
    int ct = blockIdx.x & 15;
    int cb = ct * 64;
    for (int f = tid; f < NM*NDK/4; f += 256)
        *reinterpret_cast<float4*>(&ks[f*4]) =
            *reinterpret_cast<const float4*>(&g_k[(size_t)b*NM*NDK + f*4]);
    #pragma unroll
    for (int it = 0; it < 4; it++) {
        int f = it*256 + tid;
        int m = f >> 6, c = f & 63;
        int r = b*NM + m;
        size_t ix = (size_t)r*ND + cb + c;
        float kz   = g_kz[r] + EPSV;
        float gate = 1.f/(1.f + expf(-g_g[ix]));
        nis[m*64 + c] = gate*(g_v[ix] - g_p[ix]/kz);
    }
    __syncthreads();
    const float* Wprev = &g_W[((size_t)seg*NB + b)*NDK*ND];
    float*       Wnext = &g_W[((size_t)(seg+1)*NB + b)*NDK*ND];
    int c = tid & 63, quad = tid >> 6;
    for (int kk = quad*32; kk < quad*32 + 32; kk++) {
        float a = 0.f;
        #pragma unroll
        for (int m = 0; m < NM; m++) a += ks[m*NDK + kk]*nis[m*64 + c];
        size_t ix = (size_t)kk*ND + cb + c;
        Wnext[ix] = Wprev[ix] + a;
    }
    if (ct == 0 && tid < NDK) {
        float s = g_z[((size_t)seg*NB + b)*NDK + tid];
        #pragma unroll
        for (int m = 0; m < NM; m++) s += ks[m*NDK + tid];
        g_z[((size_t)(seg+1)*NB + b)*NDK + tid] = s;
    }
}

// ---------------- K4: out = mo + tanh((Q @ W_hist[seg]) / (Q.z + eps)) ----------------
// grid (16 coltiles, 9 rowtiles, 32 = b*8+seg) x 256 thr; block 64x64, K=128
__global__ void k4_out(const float* __restrict__ mo, float* __restrict__ out)
{
    __shared__ float Qs[32*64];   // [k][r]
    __shared__ float Ws[32*64];   // [k][c]
    __shared__ float zsm[NDK];
    __shared__ float den_s[64];
    int tid = threadIdx.x;
    int cb = blockIdx.x * 64;
    int r0 = blockIdx.y * 64;
    int bs = blockIdx.z;
    int b = bs >> 3, seg = bs & 7;
    const float* Wp = &g_W[((size_t)seg*NB + b)*NDK*ND];
    if (tid < NDK) zsm[tid] = g_z[((size_t)seg*NB + b)*NDK + tid];
    int tx = tid & 15, ty = tid >> 4;
    float acc[4][4];
    #pragma unroll
    for (int i = 0; i < 4; i++)
        #pragma unroll
        for (int j = 0; j < 4; j++) acc[i][j] = 0.f;
    float den = 0.f;
    size_t qbase = ((size_t)b*NS + seg*NL + r0)*NDK;

    for (int k0 = 0; k0 < NDK; k0 += 32) {
        __syncthreads();
        #pragma unroll
        for (int it = 0; it < 2; it++) {           // Q: 64x32 = 512 float4
            int f = it*256 + tid;
            int r = f >> 3; int q = (f & 7) * 4;
            int rr = (r0 + r < NL) ? r : 0;        // clamp tail rows
            float4 v4 = *reinterpret_cast<const float4*>(
                &g_Q[qbase + (size_t)rr*NDK + k0 + q]);
            Qs[(q+0)*64+r] = v4.x; Qs[(q+1)*64+r] = v4.y;
            Qs[(q+2)*64+r] = v4.z; Qs[(q+3)*64+r] = v4.w;
        }
        #pragma unroll
        for (int it = 0; it < 2; it++) {           // W: 32x64 = 512 float4
            int f = it*256 + tid;
            int kr = f >> 4; int c = (f & 15) * 4;
            *reinterpret_cast<float4*>(&Ws[kr*64 + c]) =
                *reinterpret_cast<const float4*>(&Wp[(size_t)(k0 + kr)*ND + cb + c]);
        }
        __syncthreads();
        if (tid < 64) {
            float d2 = 0.f;
            #pragma unroll
            for (int k = 0; k < 32; k++) d2 += Qs[k*64 + tid]*zsm[k0 + k];
            den += d2;
        }
        #pragma unroll
        for (int k = 0; k < 32; k++) {
            float ra[4], rb[4];
            #pragma unroll
            for (int i = 0; i < 4; i++) ra[i] = Qs[k*64 + ty*4 + i];
            #pragma unroll
            for (int j = 0; j < 4; j++) rb[j] = Ws[k*64 + tx*4 + j];
            #pragma unroll
            for (int i = 0; i < 4; i++)
                #pragma unroll
                for (int j = 0; j < 4; j++) acc[i][j] += ra[i]*rb[j];
        }
    }
    if (tid < 64) den_s[tid] = den;
    __syncthreads();
    #pragma unroll
    for (int i = 0; i < 4; i++) {
        int r = ty*4 + i;
        if (r0 + r >= NL) continue;
        float de = den_s[r] + EPSV;
        int s = seg*NL + r0 + r;
        size_t ob = ((size_t)b*NS + s)*ND + cb;
        #pragma unroll
        for (int j = 0; j < 4; j++) {
            int d = tx*4 + j;
            out[ob + d] = mo[ob + d] + tanhf(acc[i][j]/de);
        }
    }
}

// ---------------- launch ----------------
extern "C" void kernel_launch(void* const* d_in, const int* in_sizes, int n_in,
                              void* d_out, int out_size)
{
    const float* hs  = (const float*)d_in[0];
    const float* mo  = (const float*)d_in[1];
    const float* Wmq = (const float*)d_in[2];
    const float* Wmk = (const float*)d_in[3];
    const float* Wmv = (const float*)d_in[4];
    const float* Wmb = (const float*)d_in[5];
    const float* bmb = (const float*)d_in[6];
    float* out = (float*)d_out;

    k_init<<<2048, 256>>>();
    k0_projq<<<132, 256>>>(hs, Wmq);
    for (int seg = 0; seg < NSEG; seg++) {
        k1_assoc<<<64, 256>>>(mo, seg);
        k2a_x<<<16, 256>>>(seg, Wmk);
        k2b_vgp<<<192, 256>>>(seg, Wmv, Wmb, bmb);
        k3_update<<<64, 256>>>(seg);
    }
    k4_out<<<dim3(16, 9, 32), 256>>>(mo, out);
}